// round 13
// baseline (speedup 1.0000x reference)
#include <cuda_runtime.h>
#include <math.h>

#define NN   6000
#define EE   192000
#define DIN  512
#define HH   128
#define NPB  16          // nodes per block in p-kernel (halves w_emb L2 traffic)
#define EOSF 1e-10f

// Scratch (__device__ globals allowed; heap allocs are not).
__device__ int   g_win[(size_t)NN * NN];   // winner edge-index+1 per cell (only edge cells touched)
__device__ float g_p[NN];
__device__ float g_dlp[NN];
__device__ float g_dhp[NN];
__device__ float g_ilp[NN];
__device__ float g_ihp[NN];

// SM-side zero fill (write-through float4 stores — best measured variant).
__global__ void __launch_bounds__(512) k_fill(float4* __restrict__ dst, size_t n4) {
    size_t i = (size_t)blockIdx.x * blockDim.x + threadIdx.x;
    size_t stride = (size_t)gridDim.x * blockDim.x;
    const float4 z = make_float4(0.f, 0.f, 0.f, 0.f);
    for (; i < n4; i += stride) __stwt(dst + i, z);
}

// Clear winner at all edge cells; init degrees to 1.0 (the +eye term in row sums).
__global__ void k_clear(const int* __restrict__ edges) {
    int t = blockIdx.x * blockDim.x + threadIdx.x;
    if (t < EE) {
        int u = edges[t], v = edges[EE + t];
        g_win[u * NN + v] = 0;
    }
    if (t < NN) { g_dlp[t] = 1.0f; g_dhp[t] = 1.0f; }
}

// Last-edge-wins dedup: winner = max edge index + 1.
__global__ void k_max(const int* __restrict__ edges) {
    int e = blockIdx.x * blockDim.x + threadIdx.x;
    if (e >= EE) return;
    int u = edges[e], v = edges[EE + e];
    atomicMax(&g_win[u * NN + v], e + 1);
}

// p[n] = sum_h relu(feat[n]·w_emb[:,h] + b_emb[h]) * (w_mlp[h] + w_mlp[H+h])
__global__ void __launch_bounds__(HH) k_p(const float* __restrict__ feat,
                                          const float* __restrict__ wemb,
                                          const float* __restrict__ bemb,
                                          const float* __restrict__ wmlp) {
    __shared__ float sf[NPB][DIN];
    int h  = threadIdx.x;
    int n0 = blockIdx.x * NPB;

    const float4* f4 = (const float4*)(feat + (size_t)n0 * DIN);
    float4* s4 = (float4*)&sf[0][0];
    const int total4 = NPB * DIN / 4;
    for (int i = h; i < total4; i += HH) s4[i] = f4[i];
    __syncthreads();

    float acc[NPB];
#pragma unroll
    for (int j = 0; j < NPB; j++) acc[j] = 0.0f;

    for (int d = 0; d < DIN; d += 4) {
        float w0 = wemb[(d + 0) * HH + h];
        float w1 = wemb[(d + 1) * HH + h];
        float w2 = wemb[(d + 2) * HH + h];
        float w3 = wemb[(d + 3) * HH + h];
#pragma unroll
        for (int j = 0; j < NPB; j++) {
            float4 f = *(const float4*)&sf[j][d];
            acc[j] = fmaf(f.x, w0, acc[j]);
            acc[j] = fmaf(f.y, w1, acc[j]);
            acc[j] = fmaf(f.z, w2, acc[j]);
            acc[j] = fmaf(f.w, w3, acc[j]);
        }
    }

    float b  = bemb[h];
    float ws = wmlp[h] + wmlp[HH + h];
    __shared__ float red[4][NPB];
#pragma unroll
    for (int j = 0; j < NPB; j++) {
        float v = acc[j] + b;
        v = (v > 0.0f) ? v * ws : 0.0f;
#pragma unroll
        for (int off = 16; off; off >>= 1) v += __shfl_down_sync(0xffffffffu, v, off);
        if ((h & 31) == 0) red[h >> 5][j] = v;
    }
    __syncthreads();
    if (h < NPB)
        g_p[n0 + h] = red[0][h] + red[1][h] + red[2][h] + red[3][h];
}

// Per-edge gating weights + winner-only degree accumulation (row sums).
__global__ void k_edge(const int* __restrict__ edges, const float* __restrict__ gn,
                       const float* __restrict__ bmlp,
                       float* __restrict__ wlp_out, float* __restrict__ whp_out) {
    int e = blockIdx.x * blockDim.x + threadIdx.x;
    if (e >= EE) return;
    int u = edges[e], v = edges[EE + e];
    float raw = 0.5f * (g_p[u] + g_p[v]) + bmlp[0];
    float x   = gn[e] + raw;               // TEMP = 1
    float wlp = 1.0f / (1.0f + expf(-x));
    wlp_out[e] = wlp;
    whp_out[e] = 1.0f - wlp;
    if (g_win[u * NN + v] == e + 1) {       // deduped adjacency contribution
        atomicAdd(&g_dlp[u], wlp);
        atomicAdd(&g_dhp[u], 1.0f - wlp);
    }
}

__global__ void k_inv() {
    int i = blockIdx.x * blockDim.x + threadIdx.x;
    if (i >= NN) return;
    g_ilp[i] = 1.0f / (sqrtf(g_dlp[i]) + EOSF);
    g_ihp[i] = 1.0f / (sqrtf(g_dhp[i]) + EOSF);
}

// Unnorm/mask scatter: duplicates write the same value.
__global__ void k_fin_unnorm(const int* __restrict__ edges, float* __restrict__ unnorm) {
    int t = blockIdx.x * blockDim.x + threadIdx.x;
    if (t >= EE) return;
    int u = edges[t], v = edges[EE + t];
    __stcs(&unnorm[(size_t)u * NN + v], 1.0f);
}

// Fused adjacency scatter + diagonal (R6 tail, unchanged). Pure stores, no RMW.
__global__ void k_fin_adj(const int* __restrict__ edges, const float* __restrict__ wlp_out,
                          float* __restrict__ adj_lp, float* __restrict__ adj_hp) {
    int t = blockIdx.x * blockDim.x + threadIdx.x;
    if (t < EE) {
        int u = edges[t], v = edges[EE + t];
        size_t cell = (size_t)u * NN + v;
        if (g_win[cell] == t + 1) {
            float wlp = wlp_out[t];
            float il = g_ilp[u] * g_ilp[v];
            float ih = g_ihp[u] * g_ihp[v];
            if (u == v) {
                __stcs(&adj_lp[cell], (1.0f + wlp) * il);          // eye + self-edge, normalized
                __stcs(&adj_hp[cell], 1.0f - (2.0f - wlp) * ih);   // 1 - (whp + 1)*ih
            } else {
                __stcs(&adj_lp[cell], wlp * il);
                __stcs(&adj_hp[cell], -(1.0f - wlp) * ih);
            }
        }
    } else if (t < EE + NN) {
        int i = t - EE;
        size_t cell = (size_t)i * NN + i;
        if (g_win[cell] == 0) {              // no self-edge at (i,i)
            float il = g_ilp[i];
            __stcs(&adj_lp[cell], il * il);
            __stcs(&adj_hp[cell], 1.0f);
        }
    }
}

extern "C" void kernel_launch(void* const* d_in, const int* in_sizes, int n_in,
                              void* d_out, int out_size) {
    const float* feat  = (const float*)d_in[0];
    const int*   edges = (const int*)  d_in[1];
    const float* wemb  = (const float*)d_in[2];
    const float* bemb  = (const float*)d_in[3];
    const float* wmlp  = (const float*)d_in[4];
    const float* bmlp  = (const float*)d_in[5];
    const float* gn    = (const float*)d_in[6];

    float* out     = (float*)d_out;
    float* adj_lp  = out;
    float* adj_hp  = out + (size_t)NN * NN;
    float* wlp     = out + 2ull * NN * NN;
    float* whp     = wlp + EE;
    float* unnorm  = whp + EE;

    static cudaStream_t s_f = nullptr, s_c = nullptr;
    static cudaEvent_t ev_fork = nullptr, ev_u = nullptr, ev_adj = nullptr,
                       ev_chain = nullptr;
    if (!s_f) {
        cudaStreamCreateWithFlags(&s_f, cudaStreamNonBlocking);
        cudaStreamCreateWithFlags(&s_c, cudaStreamNonBlocking);
        cudaEventCreateWithFlags(&ev_fork,  cudaEventDisableTiming);
        cudaEventCreateWithFlags(&ev_u,     cudaEventDisableTiming);
        cudaEventCreateWithFlags(&ev_adj,   cudaEventDisableTiming);
        cudaEventCreateWithFlags(&ev_chain, cudaEventDisableTiming);
    }

    const int TB = 256;
    const size_t MAT = (size_t)NN * NN;   // elements per matrix
    const int FG = 148 * 16;

    // Fork.
    cudaEventRecord(ev_fork, 0);
    cudaStreamWaitEvent(s_f, ev_fork, 0);
    cudaStreamWaitEvent(s_c, ev_fork, 0);

    // Fill stream (R6 order, unshared): unnorm first, adjacency (288 MB) second.
    k_fill<<<FG, 512, 0, s_f>>>((float4*)unnorm, MAT / 4);
    cudaEventRecord(ev_u, s_f);
    k_fill<<<FG, 512, 0, s_f>>>((float4*)adj_lp, (2ull * MAT) / 4);
    cudaEventRecord(ev_adj, s_f);

    // Compute chain — fully serialized on ONE stream so at most one compute
    // kernel contends with the fill at any instant.
    k_clear<<<(EE + TB - 1) / TB, TB, 0, s_c>>>(edges);
    k_max  <<<(EE + TB - 1) / TB, TB, 0, s_c>>>(edges);
    k_p    <<<NN / NPB, HH, 0, s_c>>>(feat, wemb, bemb, wmlp);
    k_edge <<<(EE + TB - 1) / TB, TB, 0, s_c>>>(edges, gn, bmlp, wlp, whp);
    k_inv  <<<(NN + TB - 1) / TB, TB, 0, s_c>>>();
    cudaStreamWaitEvent(s_c, ev_u, 0);
    k_fin_unnorm<<<(EE + TB - 1) / TB, TB, 0, s_c>>>(edges, unnorm);
    cudaEventRecord(ev_chain, s_c);

    // Tail on default stream: after the adj fill drains and the chain is done.
    cudaStreamWaitEvent(0, ev_adj, 0);
    cudaStreamWaitEvent(0, ev_chain, 0);
    k_fin_adj<<<(EE + NN + TB - 1) / TB, TB>>>(edges, wlp, adj_lp, adj_hp);
}

// round 14
// speedup vs baseline: 1.1024x; 1.1024x over previous
#include <cuda_runtime.h>
#include <math.h>

#define NN   6000
#define EE   192000
#define DIN  512
#define HH   128
#define NPB  8           // nodes per block in p-kernel
#define EOSF 1e-10f

// Scratch (__device__ globals allowed; heap allocs are not).
__device__ int   g_win[(size_t)NN * NN];   // winner edge-index+1 per cell (only edge cells touched)
__device__ float g_p[NN];
__device__ float g_dlp[NN];
__device__ float g_dhp[NN];
__device__ float g_ilp[NN];
__device__ float g_ihp[NN];

// Zero fill with write-through stores: best measured fill variant.
__global__ void __launch_bounds__(512) k_fill(float4* __restrict__ dst, size_t n4) {
    size_t i = (size_t)blockIdx.x * blockDim.x + threadIdx.x;
    size_t stride = (size_t)gridDim.x * blockDim.x;
    const float4 z = make_float4(0.f, 0.f, 0.f, 0.f);
    for (; i < n4; i += stride) __stwt(dst + i, z);
}

// Clear winner at all edge cells; init degrees to 1.0 (the +eye term in row sums).
__global__ void k_clear(const int* __restrict__ edges) {
    int t = blockIdx.x * blockDim.x + threadIdx.x;
    if (t < EE) {
        int u = edges[t], v = edges[EE + t];
        g_win[u * NN + v] = 0;
    }
    if (t < NN) { g_dlp[t] = 1.0f; g_dhp[t] = 1.0f; }
}

// Last-edge-wins dedup: winner = max edge index + 1.
__global__ void k_max(const int* __restrict__ edges) {
    int e = blockIdx.x * blockDim.x + threadIdx.x;
    if (e >= EE) return;
    int u = edges[e], v = edges[EE + e];
    atomicMax(&g_win[u * NN + v], e + 1);
}

// p[n] = sum_h relu(feat[n]·w_emb[:,h] + b_emb[h]) * (w_mlp[h] + w_mlp[H+h])
__global__ void __launch_bounds__(HH) k_p(const float* __restrict__ feat,
                                          const float* __restrict__ wemb,
                                          const float* __restrict__ bemb,
                                          const float* __restrict__ wmlp) {
    __shared__ float sf[NPB][DIN];
    int h  = threadIdx.x;
    int n0 = blockIdx.x * NPB;

    const float4* f4 = (const float4*)(feat + (size_t)n0 * DIN);
    float4* s4 = (float4*)&sf[0][0];
    const int total4 = NPB * DIN / 4;
    for (int i = h; i < total4; i += HH) s4[i] = f4[i];
    __syncthreads();

    float acc[NPB];
#pragma unroll
    for (int j = 0; j < NPB; j++) acc[j] = 0.0f;

    for (int d = 0; d < DIN; d += 4) {
        float w0 = wemb[(d + 0) * HH + h];
        float w1 = wemb[(d + 1) * HH + h];
        float w2 = wemb[(d + 2) * HH + h];
        float w3 = wemb[(d + 3) * HH + h];
#pragma unroll
        for (int j = 0; j < NPB; j++) {
            float4 f = *(const float4*)&sf[j][d];
            acc[j] = fmaf(f.x, w0, acc[j]);
            acc[j] = fmaf(f.y, w1, acc[j]);
            acc[j] = fmaf(f.z, w2, acc[j]);
            acc[j] = fmaf(f.w, w3, acc[j]);
        }
    }

    float b  = bemb[h];
    float ws = wmlp[h] + wmlp[HH + h];
    __shared__ float red[4][NPB];
#pragma unroll
    for (int j = 0; j < NPB; j++) {
        float v = acc[j] + b;
        v = (v > 0.0f) ? v * ws : 0.0f;
#pragma unroll
        for (int off = 16; off; off >>= 1) v += __shfl_down_sync(0xffffffffu, v, off);
        if ((h & 31) == 0) red[h >> 5][j] = v;
    }
    __syncthreads();
    if (h < NPB)
        g_p[n0 + h] = red[0][h] + red[1][h] + red[2][h] + red[3][h];
}

// Per-edge gating weights + winner-only degree accumulation (row sums).
__global__ void k_edge(const int* __restrict__ edges, const float* __restrict__ gn,
                       const float* __restrict__ bmlp,
                       float* __restrict__ wlp_out, float* __restrict__ whp_out) {
    int e = blockIdx.x * blockDim.x + threadIdx.x;
    if (e >= EE) return;
    int u = edges[e], v = edges[EE + e];
    float raw = 0.5f * (g_p[u] + g_p[v]) + bmlp[0];
    float x   = gn[e] + raw;               // TEMP = 1
    float wlp = 1.0f / (1.0f + expf(-x));
    wlp_out[e] = wlp;
    whp_out[e] = 1.0f - wlp;
    if (g_win[u * NN + v] == e + 1) {       // deduped adjacency contribution
        atomicAdd(&g_dlp[u], wlp);
        atomicAdd(&g_dhp[u], 1.0f - wlp);
    }
}

__global__ void k_inv() {
    int i = blockIdx.x * blockDim.x + threadIdx.x;
    if (i >= NN) return;
    g_ilp[i] = 1.0f / (sqrtf(g_dlp[i]) + EOSF);
    g_ihp[i] = 1.0f / (sqrtf(g_dhp[i]) + EOSF);
}

// Unnorm/mask scatter: duplicates write the same value.
__global__ void k_fin_unnorm(const int* __restrict__ edges, float* __restrict__ unnorm) {
    int t = blockIdx.x * blockDim.x + threadIdx.x;
    if (t >= EE) return;
    int u = edges[t], v = edges[EE + t];
    __stcs(&unnorm[(size_t)u * NN + v], 1.0f);
}

// Fused adjacency scatter + diagonal. Pure stores, no RMW (self-edge closed-form).
__global__ void k_fin_adj(const int* __restrict__ edges, const float* __restrict__ wlp_out,
                          float* __restrict__ adj_lp, float* __restrict__ adj_hp) {
    int t = blockIdx.x * blockDim.x + threadIdx.x;
    if (t < EE) {
        int u = edges[t], v = edges[EE + t];
        size_t cell = (size_t)u * NN + v;
        if (g_win[cell] == t + 1) {
            float wlp = wlp_out[t];
            float il = g_ilp[u] * g_ilp[v];
            float ih = g_ihp[u] * g_ihp[v];
            if (u == v) {
                __stcs(&adj_lp[cell], (1.0f + wlp) * il);          // eye + self-edge, normalized
                __stcs(&adj_hp[cell], 1.0f - (2.0f - wlp) * ih);   // 1 - (whp + 1)*ih
            } else {
                __stcs(&adj_lp[cell], wlp * il);
                __stcs(&adj_hp[cell], -(1.0f - wlp) * ih);
            }
        }
    } else if (t < EE + NN) {
        int i = t - EE;
        size_t cell = (size_t)i * NN + i;
        if (g_win[cell] == 0) {              // no self-edge at (i,i)
            float il = g_ilp[i];
            __stcs(&adj_lp[cell], il * il);
            __stcs(&adj_hp[cell], 1.0f);
        }
    }
}

extern "C" void kernel_launch(void* const* d_in, const int* in_sizes, int n_in,
                              void* d_out, int out_size) {
    const float* feat  = (const float*)d_in[0];
    const int*   edges = (const int*)  d_in[1];
    const float* wemb  = (const float*)d_in[2];
    const float* bemb  = (const float*)d_in[3];
    const float* wmlp  = (const float*)d_in[4];
    const float* bmlp  = (const float*)d_in[5];
    const float* gn    = (const float*)d_in[6];

    float* out     = (float*)d_out;
    float* adj_lp  = out;
    float* adj_hp  = out + (size_t)NN * NN;
    float* wlp     = out + 2ull * NN * NN;
    float* whp     = wlp + EE;
    float* unnorm  = whp + EE;

    static cudaStream_t s_sm = nullptr, s_p = nullptr;
    static cudaEvent_t ev_fork = nullptr, ev_fu = nullptr, ev_fa = nullptr,
                       ev_p = nullptr, ev_un = nullptr;
    if (!s_sm) {
        cudaStreamCreateWithFlags(&s_sm, cudaStreamNonBlocking);
        cudaStreamCreateWithFlags(&s_p,  cudaStreamNonBlocking);
        cudaEventCreateWithFlags(&ev_fork, cudaEventDisableTiming);
        cudaEventCreateWithFlags(&ev_fu,   cudaEventDisableTiming);
        cudaEventCreateWithFlags(&ev_fa,   cudaEventDisableTiming);
        cudaEventCreateWithFlags(&ev_p,    cudaEventDisableTiming);
        cudaEventCreateWithFlags(&ev_un,   cudaEventDisableTiming);
    }

    const int TB = 256;
    const size_t MAT = (size_t)NN * NN;   // elements per matrix
    const int FG = 148 * 16;

    // Fork.
    cudaEventRecord(ev_fork, 0);
    cudaStreamWaitEvent(s_sm, ev_fork, 0);
    cudaStreamWaitEvent(s_p,  ev_fork, 0);

    // Fill stream: unnorm first (its scatter has no other dependencies), then
    // the two adjacency matrices (contiguous, 288 MB).
    k_fill<<<FG, 512, 0, s_sm>>>((float4*)unnorm, MAT / 4);
    cudaEventRecord(ev_fu, s_sm);
    k_fill<<<FG, 512, 0, s_sm>>>((float4*)adj_lp, (2ull * MAT) / 4);
    cudaEventRecord(ev_fa, s_sm);

    // p stream: node scalar projection, then unnorm scatter once its fill lands.
    k_p<<<NN / NPB, HH, 0, s_p>>>(feat, wemb, bemb, wmlp);
    cudaEventRecord(ev_p, s_p);
    cudaStreamWaitEvent(s_p, ev_fu, 0);
    k_fin_unnorm<<<(EE + TB - 1) / TB, TB, 0, s_p>>>(edges, unnorm);
    cudaEventRecord(ev_un, s_p);

    // Main chain: winner bookkeeping, gating, norms (all overlap the fills).
    k_clear<<<(EE + TB - 1) / TB, TB>>>(edges);
    k_max  <<<(EE + TB - 1) / TB, TB>>>(edges);
    cudaStreamWaitEvent(0, ev_p, 0);
    k_edge<<<(EE + TB - 1) / TB, TB>>>(edges, gn, bmlp, wlp, whp);
    k_inv <<<(NN + TB - 1) / TB, TB>>>();

    // Join adjacency fill, then the single fused scatter tail.
    cudaStreamWaitEvent(0, ev_fa, 0);
    k_fin_adj<<<(EE + NN + TB - 1) / TB, TB>>>(edges, wlp, adj_lp, adj_hp);

    // Join the unnorm branch so the graph has a single terminal.
    cudaStreamWaitEvent(0, ev_un, 0);
}

// round 15
// speedup vs baseline: 1.1067x; 1.0039x over previous
#include <cuda_runtime.h>
#include <math.h>

#define NN   6000
#define EE   192000
#define DIN  512
#define HH   128
#define NPB  8           // nodes per block in p-kernel
#define EOSF 1e-10f

// Scratch (__device__ globals allowed; heap allocs are not).
__device__ int   g_win[(size_t)NN * NN];   // winner edge-index+1 per cell (only edge cells touched)
__device__ float g_p[NN];
__device__ float g_dlp[NN];
__device__ float g_dhp[NN];
__device__ float g_ilp[NN];
__device__ float g_ihp[NN];
__device__ unsigned char g_isw[EE];        // per-edge winner flag (coalesced for the tail)

// Zero fill with write-through stores: best measured fill variant.
__global__ void __launch_bounds__(512) k_fill(float4* __restrict__ dst, size_t n4) {
    size_t i = (size_t)blockIdx.x * blockDim.x + threadIdx.x;
    size_t stride = (size_t)gridDim.x * blockDim.x;
    const float4 z = make_float4(0.f, 0.f, 0.f, 0.f);
    for (; i < n4; i += stride) __stwt(dst + i, z);
}

// Clear winner at all edge cells; init degrees to 1.0 (the +eye term in row sums).
__global__ void k_clear(const int* __restrict__ edges) {
    int t = blockIdx.x * blockDim.x + threadIdx.x;
    if (t < EE) {
        int u = edges[t], v = edges[EE + t];
        g_win[u * NN + v] = 0;
    }
    if (t < NN) { g_dlp[t] = 1.0f; g_dhp[t] = 1.0f; }
}

// Last-edge-wins dedup: winner = max edge index + 1.
__global__ void k_max(const int* __restrict__ edges) {
    int e = blockIdx.x * blockDim.x + threadIdx.x;
    if (e >= EE) return;
    int u = edges[e], v = edges[EE + e];
    atomicMax(&g_win[u * NN + v], e + 1);
}

// p[n] = sum_h relu(feat[n]·w_emb[:,h] + b_emb[h]) * (w_mlp[h] + w_mlp[H+h])
__global__ void __launch_bounds__(HH) k_p(const float* __restrict__ feat,
                                          const float* __restrict__ wemb,
                                          const float* __restrict__ bemb,
                                          const float* __restrict__ wmlp) {
    __shared__ float sf[NPB][DIN];
    int h  = threadIdx.x;
    int n0 = blockIdx.x * NPB;

    const float4* f4 = (const float4*)(feat + (size_t)n0 * DIN);
    float4* s4 = (float4*)&sf[0][0];
    const int total4 = NPB * DIN / 4;
    for (int i = h; i < total4; i += HH) s4[i] = f4[i];
    __syncthreads();

    float acc[NPB];
#pragma unroll
    for (int j = 0; j < NPB; j++) acc[j] = 0.0f;

    for (int d = 0; d < DIN; d += 4) {
        float w0 = wemb[(d + 0) * HH + h];
        float w1 = wemb[(d + 1) * HH + h];
        float w2 = wemb[(d + 2) * HH + h];
        float w3 = wemb[(d + 3) * HH + h];
#pragma unroll
        for (int j = 0; j < NPB; j++) {
            float4 f = *(const float4*)&sf[j][d];
            acc[j] = fmaf(f.x, w0, acc[j]);
            acc[j] = fmaf(f.y, w1, acc[j]);
            acc[j] = fmaf(f.z, w2, acc[j]);
            acc[j] = fmaf(f.w, w3, acc[j]);
        }
    }

    float b  = bemb[h];
    float ws = wmlp[h] + wmlp[HH + h];
    __shared__ float red[4][NPB];
#pragma unroll
    for (int j = 0; j < NPB; j++) {
        float v = acc[j] + b;
        v = (v > 0.0f) ? v * ws : 0.0f;
#pragma unroll
        for (int off = 16; off; off >>= 1) v += __shfl_down_sync(0xffffffffu, v, off);
        if ((h & 31) == 0) red[h >> 5][j] = v;
    }
    __syncthreads();
    if (h < NPB)
        g_p[n0 + h] = red[0][h] + red[1][h] + red[2][h] + red[3][h];
}

// Per-edge gating weights + winner flag + winner-only degree accumulation.
__global__ void k_edge(const int* __restrict__ edges, const float* __restrict__ gn,
                       const float* __restrict__ bmlp,
                       float* __restrict__ wlp_out, float* __restrict__ whp_out) {
    int e = blockIdx.x * blockDim.x + threadIdx.x;
    if (e >= EE) return;
    int u = edges[e], v = edges[EE + e];
    float raw = 0.5f * (g_p[u] + g_p[v]) + bmlp[0];
    float x   = gn[e] + raw;               // TEMP = 1
    float wlp = 1.0f / (1.0f + expf(-x));
    wlp_out[e] = wlp;
    whp_out[e] = 1.0f - wlp;
    int win = (g_win[u * NN + v] == e + 1);
    g_isw[e] = (unsigned char)win;          // coalesced flag for the lean tail
    if (win) {
        atomicAdd(&g_dlp[u], wlp);
        atomicAdd(&g_dhp[u], 1.0f - wlp);
    }
}

__global__ void k_inv() {
    int i = blockIdx.x * blockDim.x + threadIdx.x;
    if (i >= NN) return;
    g_ilp[i] = 1.0f / (sqrtf(g_dlp[i]) + EOSF);
    g_ihp[i] = 1.0f / (sqrtf(g_dhp[i]) + EOSF);
}

// Unnorm/mask scatter: duplicates write the same value.
__global__ void k_fin_unnorm(const int* __restrict__ edges, float* __restrict__ unnorm) {
    int t = blockIdx.x * blockDim.x + threadIdx.x;
    if (t >= EE) return;
    int u = edges[t], v = edges[EE + t];
    __stcs(&unnorm[(size_t)u * NN + v], 1.0f);
}

// Lean fused adjacency tail: coalesced flag/index/weight loads, L2-resident
// inv-norm gathers, pure random stores. No 144MB-matrix random reads for edges.
__global__ void k_fin_adj(const int* __restrict__ edges, const float* __restrict__ wlp_out,
                          float* __restrict__ adj_lp, float* __restrict__ adj_hp) {
    int t = blockIdx.x * blockDim.x + threadIdx.x;
    if (t < EE) {
        if (!g_isw[t]) return;
        int u = edges[t], v = edges[EE + t];
        size_t cell = (size_t)u * NN + v;
        float wlp = wlp_out[t];
        float il = g_ilp[u] * g_ilp[v];
        float ih = g_ihp[u] * g_ihp[v];
        if (u == v) {
            __stcs(&adj_lp[cell], (1.0f + wlp) * il);          // eye + self-edge, normalized
            __stcs(&adj_hp[cell], 1.0f - (2.0f - wlp) * ih);   // 1 - (whp + 1)*ih
        } else {
            __stcs(&adj_lp[cell], wlp * il);
            __stcs(&adj_hp[cell], -(1.0f - wlp) * ih);
        }
    } else if (t < EE + NN) {
        int i = t - EE;
        size_t cell = (size_t)i * NN + i;
        if (g_win[cell] == 0) {              // no self-edge at (i,i); 6000 reads only
            float il = g_ilp[i];
            __stcs(&adj_lp[cell], il * il);
            __stcs(&adj_hp[cell], 1.0f);
        }
    }
}

extern "C" void kernel_launch(void* const* d_in, const int* in_sizes, int n_in,
                              void* d_out, int out_size) {
    const float* feat  = (const float*)d_in[0];
    const int*   edges = (const int*)  d_in[1];
    const float* wemb  = (const float*)d_in[2];
    const float* bemb  = (const float*)d_in[3];
    const float* wmlp  = (const float*)d_in[4];
    const float* bmlp  = (const float*)d_in[5];
    const float* gn    = (const float*)d_in[6];

    float* out     = (float*)d_out;
    float* adj_lp  = out;
    float* adj_hp  = out + (size_t)NN * NN;
    float* wlp     = out + 2ull * NN * NN;
    float* whp     = wlp + EE;
    float* unnorm  = whp + EE;

    static cudaStream_t s_sm = nullptr, s_p = nullptr;
    static cudaEvent_t ev_fork = nullptr, ev_fu = nullptr, ev_p = nullptr,
                       ev_un = nullptr, ev_chain = nullptr, ev_tail = nullptr;
    if (!s_sm) {
        cudaStreamCreateWithFlags(&s_sm, cudaStreamNonBlocking);
        cudaStreamCreateWithFlags(&s_p,  cudaStreamNonBlocking);
        cudaEventCreateWithFlags(&ev_fork,  cudaEventDisableTiming);
        cudaEventCreateWithFlags(&ev_fu,    cudaEventDisableTiming);
        cudaEventCreateWithFlags(&ev_p,     cudaEventDisableTiming);
        cudaEventCreateWithFlags(&ev_un,    cudaEventDisableTiming);
        cudaEventCreateWithFlags(&ev_chain, cudaEventDisableTiming);
        cudaEventCreateWithFlags(&ev_tail,  cudaEventDisableTiming);
    }

    const int TB = 256;
    const size_t MAT = (size_t)NN * NN;   // elements per matrix
    const int FG = 148 * 16;

    // Fork.
    cudaEventRecord(ev_fork, 0);
    cudaStreamWaitEvent(s_sm, ev_fork, 0);
    cudaStreamWaitEvent(s_p,  ev_fork, 0);

    // Fill stream: unnorm first, then the two adjacency matrices (288 MB).
    k_fill<<<FG, 512, 0, s_sm>>>((float4*)unnorm, MAT / 4);
    cudaEventRecord(ev_fu, s_sm);
    k_fill<<<FG, 512, 0, s_sm>>>((float4*)adj_lp, (2ull * MAT) / 4);

    // p stream: node scalar projection, then unnorm scatter once its fill lands.
    k_p<<<NN / NPB, HH, 0, s_p>>>(feat, wemb, bemb, wmlp);
    cudaEventRecord(ev_p, s_p);
    cudaStreamWaitEvent(s_p, ev_fu, 0);
    k_fin_unnorm<<<(EE + TB - 1) / TB, TB, 0, s_p>>>(edges, unnorm);
    cudaEventRecord(ev_un, s_p);

    // Main chain: winner bookkeeping, gating, norms (all overlap the fills).
    k_clear<<<(EE + TB - 1) / TB, TB>>>(edges);
    k_max  <<<(EE + TB - 1) / TB, TB>>>(edges);
    cudaStreamWaitEvent(0, ev_p, 0);
    k_edge<<<(EE + TB - 1) / TB, TB>>>(edges, gn, bmlp, wlp, whp);
    k_inv <<<(NN + TB - 1) / TB, TB>>>();
    cudaEventRecord(ev_chain, 0);

    // Lean tail directly on the fill stream: stream-ordered after the adj fill
    // (no cross-stream hop on the critical path); chain dependency via event
    // that is long-satisfied by the time the fill drains.
    cudaStreamWaitEvent(s_sm, ev_chain, 0);
    k_fin_adj<<<(EE + NN + TB - 1) / TB, TB, 0, s_sm>>>(edges, wlp, adj_lp, adj_hp);
    cudaEventRecord(ev_tail, s_sm);

    // Join both branches so the graph has a single terminal on the default stream.
    cudaStreamWaitEvent(0, ev_tail, 0);
    cudaStreamWaitEvent(0, ev_un, 0);
}

// round 16
// speedup vs baseline: 1.1916x; 1.0767x over previous
#include <cuda_runtime.h>
#include <math.h>

#define NN   6000
#define EE   192000
#define DIN  512
#define HH   128
#define NPB  8           // nodes per block in p-kernel
#define EOSF 1e-10f
#define HTB  20
#define HTSZ (1u << HTB)
#define VMASK 0xFFFFFULL

// Scratch (__device__ globals allowed; heap allocs are not).
__device__ unsigned long long g_ht[HTSZ];  // open-addressing: (cell+1)<<20 | (e+1)
__device__ float g_p[NN];
__device__ float g_dlp[NN];
__device__ float g_dhp[NN];
__device__ float g_ilp[NN];
__device__ float g_ihp[NN];
__device__ unsigned char g_isw[EE];        // per-edge winner flag (coalesced for the tail)
__device__ unsigned char g_self[NN];       // 1 = edge (i,i) exists

__device__ __forceinline__ unsigned ht_hash(unsigned cell) {
    return (cell * 2654435761u) >> (32 - HTB);
}

// Insert-or-max: last-edge-wins dedup in an L2-resident 8 MB table.
__device__ __forceinline__ void ht_insert_max(unsigned cell, int e) {
    unsigned long long newv = (((unsigned long long)(cell + 1)) << 20) | (unsigned)(e + 1);
    unsigned long long key  = newv & ~VMASK;
    unsigned h = ht_hash(cell);
    for (;;) {
        unsigned long long cur = g_ht[h];
        if (cur == 0ULL) {
            unsigned long long prev = atomicCAS(&g_ht[h], 0ULL, newv);
            if (prev == 0ULL) return;
            cur = prev;
        }
        if ((cur & ~VMASK) == key) {       // slot owns our key; keys never change
            atomicMax(&g_ht[h], newv);     // same key bits -> compares e values
            return;
        }
        h = (h + 1) & (HTSZ - 1);
    }
}

// Is edge e the winner at its cell? (All inserts complete before any lookup.)
__device__ __forceinline__ int ht_is_winner(unsigned cell, int e) {
    unsigned long long key = ((unsigned long long)(cell + 1)) << 20;
    unsigned h = ht_hash(cell);
    for (;;) {
        unsigned long long cur = g_ht[h];
        if ((cur & ~VMASK) == key) return (cur & VMASK) == (unsigned)(e + 1);
        if (cur == 0ULL) return 0;         // unreachable: key was inserted
        h = (h + 1) & (HTSZ - 1);
    }
}

// Zero fill with write-through stores: best measured fill variant.
__global__ void __launch_bounds__(512) k_fill(float4* __restrict__ dst, size_t n4) {
    size_t i = (size_t)blockIdx.x * blockDim.x + threadIdx.x;
    size_t stride = (size_t)gridDim.x * blockDim.x;
    const float4 z = make_float4(0.f, 0.f, 0.f, 0.f);
    for (; i < n4; i += stride) __stwt(dst + i, z);
}

// Clear hash table (8 MB sequential, L2-speed) + degrees + self flags.
__global__ void k_clear() {
    int t = blockIdx.x * blockDim.x + threadIdx.x;
    int stride = gridDim.x * blockDim.x;
    for (unsigned i = t; i < HTSZ; i += stride) g_ht[i] = 0ULL;
    if (t < NN) { g_dlp[t] = 1.0f; g_dhp[t] = 1.0f; g_self[t] = 0; }
}

// Last-edge-wins dedup into the hash table.
__global__ void k_max(const int* __restrict__ edges) {
    int e = blockIdx.x * blockDim.x + threadIdx.x;
    if (e >= EE) return;
    unsigned cell = (unsigned)edges[e] * NN + (unsigned)edges[EE + e];
    ht_insert_max(cell, e);
}

// p[n] = sum_h relu(feat[n]·w_emb[:,h] + b_emb[h]) * (w_mlp[h] + w_mlp[H+h])
__global__ void __launch_bounds__(HH) k_p(const float* __restrict__ feat,
                                          const float* __restrict__ wemb,
                                          const float* __restrict__ bemb,
                                          const float* __restrict__ wmlp) {
    __shared__ float sf[NPB][DIN];
    int h  = threadIdx.x;
    int n0 = blockIdx.x * NPB;

    const float4* f4 = (const float4*)(feat + (size_t)n0 * DIN);
    float4* s4 = (float4*)&sf[0][0];
    const int total4 = NPB * DIN / 4;
    for (int i = h; i < total4; i += HH) s4[i] = f4[i];
    __syncthreads();

    float acc[NPB];
#pragma unroll
    for (int j = 0; j < NPB; j++) acc[j] = 0.0f;

    for (int d = 0; d < DIN; d += 4) {
        float w0 = wemb[(d + 0) * HH + h];
        float w1 = wemb[(d + 1) * HH + h];
        float w2 = wemb[(d + 2) * HH + h];
        float w3 = wemb[(d + 3) * HH + h];
#pragma unroll
        for (int j = 0; j < NPB; j++) {
            float4 f = *(const float4*)&sf[j][d];
            acc[j] = fmaf(f.x, w0, acc[j]);
            acc[j] = fmaf(f.y, w1, acc[j]);
            acc[j] = fmaf(f.z, w2, acc[j]);
            acc[j] = fmaf(f.w, w3, acc[j]);
        }
    }

    float b  = bemb[h];
    float ws = wmlp[h] + wmlp[HH + h];
    __shared__ float red[4][NPB];
#pragma unroll
    for (int j = 0; j < NPB; j++) {
        float v = acc[j] + b;
        v = (v > 0.0f) ? v * ws : 0.0f;
#pragma unroll
        for (int off = 16; off; off >>= 1) v += __shfl_down_sync(0xffffffffu, v, off);
        if ((h & 31) == 0) red[h >> 5][j] = v;
    }
    __syncthreads();
    if (h < NPB)
        g_p[n0 + h] = red[0][h] + red[1][h] + red[2][h] + red[3][h];
}

// Per-edge gating weights + winner flag + self flag + degree accumulation.
__global__ void k_edge(const int* __restrict__ edges, const float* __restrict__ gn,
                       const float* __restrict__ bmlp,
                       float* __restrict__ wlp_out, float* __restrict__ whp_out) {
    int e = blockIdx.x * blockDim.x + threadIdx.x;
    if (e >= EE) return;
    int u = edges[e], v = edges[EE + e];
    float raw = 0.5f * (g_p[u] + g_p[v]) + bmlp[0];
    float x   = gn[e] + raw;               // TEMP = 1
    float wlp = 1.0f / (1.0f + expf(-x));
    wlp_out[e] = wlp;
    whp_out[e] = 1.0f - wlp;
    unsigned cell = (unsigned)u * NN + (unsigned)v;
    int win = ht_is_winner(cell, e);
    g_isw[e] = (unsigned char)win;
    if (win) {
        if (u == v) g_self[u] = 1;
        atomicAdd(&g_dlp[u], wlp);
        atomicAdd(&g_dhp[u], 1.0f - wlp);
    }
}

__global__ void k_inv() {
    int i = blockIdx.x * blockDim.x + threadIdx.x;
    if (i >= NN) return;
    g_ilp[i] = 1.0f / (sqrtf(g_dlp[i]) + EOSF);
    g_ihp[i] = 1.0f / (sqrtf(g_dhp[i]) + EOSF);
}

// Unnorm/mask scatter: duplicates write the same value.
__global__ void k_fin_unnorm(const int* __restrict__ edges, float* __restrict__ unnorm) {
    int t = blockIdx.x * blockDim.x + threadIdx.x;
    if (t >= EE) return;
    int u = edges[t], v = edges[EE + t];
    __stcs(&unnorm[(size_t)u * NN + v], 1.0f);
}

// Lean fused adjacency tail: coalesced flag/index/weight loads, L2-resident
// inv-norm gathers, pure random stores. No dense-matrix reads at all.
__global__ void k_fin_adj(const int* __restrict__ edges, const float* __restrict__ wlp_out,
                          float* __restrict__ adj_lp, float* __restrict__ adj_hp) {
    int t = blockIdx.x * blockDim.x + threadIdx.x;
    if (t < EE) {
        if (!g_isw[t]) return;
        int u = edges[t], v = edges[EE + t];
        size_t cell = (size_t)u * NN + v;
        float wlp = wlp_out[t];
        float il = g_ilp[u] * g_ilp[v];
        float ih = g_ihp[u] * g_ihp[v];
        if (u == v) {
            __stcs(&adj_lp[cell], (1.0f + wlp) * il);          // eye + self-edge, normalized
            __stcs(&adj_hp[cell], 1.0f - (2.0f - wlp) * ih);   // 1 - (whp + 1)*ih
        } else {
            __stcs(&adj_lp[cell], wlp * il);
            __stcs(&adj_hp[cell], -(1.0f - wlp) * ih);
        }
    } else if (t < EE + NN) {
        int i = t - EE;
        if (g_self[i]) return;               // self-edge winner covers the diagonal
        size_t cell = (size_t)i * NN + i;
        float il = g_ilp[i];
        __stcs(&adj_lp[cell], il * il);
        __stcs(&adj_hp[cell], 1.0f);
    }
}

extern "C" void kernel_launch(void* const* d_in, const int* in_sizes, int n_in,
                              void* d_out, int out_size) {
    const float* feat  = (const float*)d_in[0];
    const int*   edges = (const int*)  d_in[1];
    const float* wemb  = (const float*)d_in[2];
    const float* bemb  = (const float*)d_in[3];
    const float* wmlp  = (const float*)d_in[4];
    const float* bmlp  = (const float*)d_in[5];
    const float* gn    = (const float*)d_in[6];

    float* out     = (float*)d_out;
    float* adj_lp  = out;
    float* adj_hp  = out + (size_t)NN * NN;
    float* wlp     = out + 2ull * NN * NN;
    float* whp     = wlp + EE;
    float* unnorm  = whp + EE;

    static cudaStream_t s_sm = nullptr, s_p = nullptr;
    static cudaEvent_t ev_fork = nullptr, ev_fu = nullptr, ev_fa = nullptr,
                       ev_p = nullptr, ev_un = nullptr;
    if (!s_sm) {
        cudaStreamCreateWithFlags(&s_sm, cudaStreamNonBlocking);
        cudaStreamCreateWithFlags(&s_p,  cudaStreamNonBlocking);
        cudaEventCreateWithFlags(&ev_fork, cudaEventDisableTiming);
        cudaEventCreateWithFlags(&ev_fu,   cudaEventDisableTiming);
        cudaEventCreateWithFlags(&ev_fa,   cudaEventDisableTiming);
        cudaEventCreateWithFlags(&ev_p,    cudaEventDisableTiming);
        cudaEventCreateWithFlags(&ev_un,   cudaEventDisableTiming);
    }

    const int TB = 256;
    const size_t MAT = (size_t)NN * NN;   // elements per matrix
    const int FG = 148 * 16;

    // Fork.
    cudaEventRecord(ev_fork, 0);
    cudaStreamWaitEvent(s_sm, ev_fork, 0);
    cudaStreamWaitEvent(s_p,  ev_fork, 0);

    // Fill stream: unnorm first, then the two adjacency matrices (288 MB).
    k_fill<<<FG, 512, 0, s_sm>>>((float4*)unnorm, MAT / 4);
    cudaEventRecord(ev_fu, s_sm);
    k_fill<<<FG, 512, 0, s_sm>>>((float4*)adj_lp, (2ull * MAT) / 4);
    cudaEventRecord(ev_fa, s_sm);

    // p stream: node scalar projection, then unnorm scatter once its fill lands.
    k_p<<<NN / NPB, HH, 0, s_p>>>(feat, wemb, bemb, wmlp);
    cudaEventRecord(ev_p, s_p);
    cudaStreamWaitEvent(s_p, ev_fu, 0);
    k_fin_unnorm<<<(EE + TB - 1) / TB, TB, 0, s_p>>>(edges, unnorm);
    cudaEventRecord(ev_un, s_p);

    // Main chain: hash clear, dedup, gating, norms (all overlap the fills;
    // all dedup traffic is L2-resident — no dense winner matrix).
    k_clear<<<(EE + TB - 1) / TB, TB>>>();
    k_max  <<<(EE + TB - 1) / TB, TB>>>(edges);
    cudaStreamWaitEvent(0, ev_p, 0);
    k_edge <<<(EE + TB - 1) / TB, TB>>>(edges, gn, bmlp, wlp, whp);
    k_inv  <<<(NN + TB - 1) / TB, TB>>>();

    // Join adjacency fill, then the single fused scatter tail.
    cudaStreamWaitEvent(0, ev_fa, 0);
    k_fin_adj<<<(EE + NN + TB - 1) / TB, TB>>>(edges, wlp, adj_lp, adj_hp);

    // Join the unnorm branch so the graph has a single terminal.
    cudaStreamWaitEvent(0, ev_un, 0);
}

// round 17
// speedup vs baseline: 1.2015x; 1.0083x over previous
#include <cuda_runtime.h>
#include <math.h>

#define NN   6000
#define EE   192000
#define DIN  512
#define HH   128
#define NPB  8           // nodes per block in p-kernel
#define EOSF 1e-10f
#define HTB  20
#define HTSZ (1u << HTB)
#define VMASK 0xFFFFFULL

// Scratch (__device__ globals allowed; heap allocs are not).
__device__ unsigned long long g_ht[HTSZ];  // open-addressing: (cell+1)<<20 | (e+1)
__device__ float g_p[NN];
__device__ float g_dlp[NN];
__device__ float g_dhp[NN];
__device__ float g_ilp[NN];
__device__ float g_ihp[NN];
__device__ unsigned char g_isw[EE];        // per-edge winner flag (coalesced for the tail)
__device__ unsigned char g_self[NN];       // 1 = winner self-edge (i,i) exists

__device__ __forceinline__ unsigned ht_hash(unsigned cell) {
    return (cell * 2654435761u) >> (32 - HTB);
}

// Insert-or-max: last-edge-wins dedup in an L2-resident 8 MB table.
__device__ __forceinline__ void ht_insert_max(unsigned cell, int e) {
    unsigned long long newv = (((unsigned long long)(cell + 1)) << 20) | (unsigned)(e + 1);
    unsigned long long key  = newv & ~VMASK;
    unsigned h = ht_hash(cell);
    for (;;) {
        unsigned long long cur = g_ht[h];
        if (cur == 0ULL) {
            unsigned long long prev = atomicCAS(&g_ht[h], 0ULL, newv);
            if (prev == 0ULL) return;
            cur = prev;
        }
        if ((cur & ~VMASK) == key) {       // slot owns our key; keys never change
            atomicMax(&g_ht[h], newv);     // same key bits -> compares e values
            return;
        }
        h = (h + 1) & (HTSZ - 1);
    }
}

// Is edge e the winner at its cell? (All inserts complete before any lookup.)
__device__ __forceinline__ int ht_is_winner(unsigned cell, int e) {
    unsigned long long key = ((unsigned long long)(cell + 1)) << 20;
    unsigned h = ht_hash(cell);
    for (;;) {
        unsigned long long cur = g_ht[h];
        if ((cur & ~VMASK) == key) return (cur & VMASK) == (unsigned)(e + 1);
        if (cur == 0ULL) return 0;         // unreachable: key was inserted
        h = (h + 1) & (HTSZ - 1);
    }
}

// Zero fill with write-through stores: best measured fill variant.
__global__ void __launch_bounds__(512) k_fill(float4* __restrict__ dst, size_t n4) {
    size_t i = (size_t)blockIdx.x * blockDim.x + threadIdx.x;
    size_t stride = (size_t)gridDim.x * blockDim.x;
    const float4 z = make_float4(0.f, 0.f, 0.f, 0.f);
    for (; i < n4; i += stride) __stwt(dst + i, z);
}

// Clear hash table (8 MB sequential, L2-speed) + degrees + self flags.
__global__ void k_clear() {
    int t = blockIdx.x * blockDim.x + threadIdx.x;
    int stride = gridDim.x * blockDim.x;
    for (unsigned i = t; i < HTSZ; i += stride) g_ht[i] = 0ULL;
    if (t < NN) { g_dlp[t] = 1.0f; g_dhp[t] = 1.0f; g_self[t] = 0; }
}

// Last-edge-wins dedup into the hash table.
__global__ void k_max(const int* __restrict__ edges) {
    int e = blockIdx.x * blockDim.x + threadIdx.x;
    if (e >= EE) return;
    unsigned cell = (unsigned)edges[e] * NN + (unsigned)edges[EE + e];
    ht_insert_max(cell, e);
}

// p[n] = sum_h relu(feat[n]·w_emb[:,h] + b_emb[h]) * (w_mlp[h] + w_mlp[H+h])
__global__ void __launch_bounds__(HH) k_p(const float* __restrict__ feat,
                                          const float* __restrict__ wemb,
                                          const float* __restrict__ bemb,
                                          const float* __restrict__ wmlp) {
    __shared__ float sf[NPB][DIN];
    int h  = threadIdx.x;
    int n0 = blockIdx.x * NPB;

    const float4* f4 = (const float4*)(feat + (size_t)n0 * DIN);
    float4* s4 = (float4*)&sf[0][0];
    const int total4 = NPB * DIN / 4;
    for (int i = h; i < total4; i += HH) s4[i] = f4[i];
    __syncthreads();

    float acc[NPB];
#pragma unroll
    for (int j = 0; j < NPB; j++) acc[j] = 0.0f;

    for (int d = 0; d < DIN; d += 4) {
        float w0 = wemb[(d + 0) * HH + h];
        float w1 = wemb[(d + 1) * HH + h];
        float w2 = wemb[(d + 2) * HH + h];
        float w3 = wemb[(d + 3) * HH + h];
#pragma unroll
        for (int j = 0; j < NPB; j++) {
            float4 f = *(const float4*)&sf[j][d];
            acc[j] = fmaf(f.x, w0, acc[j]);
            acc[j] = fmaf(f.y, w1, acc[j]);
            acc[j] = fmaf(f.z, w2, acc[j]);
            acc[j] = fmaf(f.w, w3, acc[j]);
        }
    }

    float b  = bemb[h];
    float ws = wmlp[h] + wmlp[HH + h];
    __shared__ float red[4][NPB];
#pragma unroll
    for (int j = 0; j < NPB; j++) {
        float v = acc[j] + b;
        v = (v > 0.0f) ? v * ws : 0.0f;
#pragma unroll
        for (int off = 16; off; off >>= 1) v += __shfl_down_sync(0xffffffffu, v, off);
        if ((h & 31) == 0) red[h >> 5][j] = v;
    }
    __syncthreads();
    if (h < NPB)
        g_p[n0 + h] = red[0][h] + red[1][h] + red[2][h] + red[3][h];
}

// Per-edge gating weights + winner flag + self flag + degree accumulation.
__global__ void k_edge(const int* __restrict__ edges, const float* __restrict__ gn,
                       const float* __restrict__ bmlp,
                       float* __restrict__ wlp_out, float* __restrict__ whp_out) {
    int e = blockIdx.x * blockDim.x + threadIdx.x;
    if (e >= EE) return;
    int u = edges[e], v = edges[EE + e];
    float raw = 0.5f * (g_p[u] + g_p[v]) + bmlp[0];
    float x   = gn[e] + raw;               // TEMP = 1
    float wlp = 1.0f / (1.0f + expf(-x));
    wlp_out[e] = wlp;
    whp_out[e] = 1.0f - wlp;
    unsigned cell = (unsigned)u * NN + (unsigned)v;
    int win = ht_is_winner(cell, e);
    g_isw[e] = (unsigned char)win;
    if (win) {
        if (u == v) g_self[u] = 1;
        atomicAdd(&g_dlp[u], wlp);
        atomicAdd(&g_dhp[u], 1.0f - wlp);
    }
}

__global__ void k_inv() {
    int i = blockIdx.x * blockDim.x + threadIdx.x;
    if (i >= NN) return;
    g_ilp[i] = 1.0f / (sqrtf(g_dlp[i]) + EOSF);
    g_ihp[i] = 1.0f / (sqrtf(g_dhp[i]) + EOSF);
}

// Unnorm/mask scatter: duplicates write the same value.
__global__ void k_fin_unnorm(const int* __restrict__ edges, float* __restrict__ unnorm) {
    int t = blockIdx.x * blockDim.x + threadIdx.x;
    if (t >= EE) return;
    int u = edges[t], v = edges[EE + t];
    __stcs(&unnorm[(size_t)u * NN + v], 1.0f);
}

// Tail half 1: adj_lp scatter + diagonal. Pure stores, coalesced metadata loads.
__global__ void k_fin_lp(const int* __restrict__ edges, const float* __restrict__ wlp_out,
                         float* __restrict__ adj_lp) {
    int t = blockIdx.x * blockDim.x + threadIdx.x;
    if (t < EE) {
        if (!g_isw[t]) return;
        int u = edges[t], v = edges[EE + t];
        float wlp = wlp_out[t];
        float il = g_ilp[u] * g_ilp[v];
        __stcs(&adj_lp[(size_t)u * NN + v], (u == v) ? (1.0f + wlp) * il : wlp * il);
    } else if (t < EE + NN) {
        int i = t - EE;
        if (g_self[i]) return;
        float il = g_ilp[i];
        __stcs(&adj_lp[(size_t)i * NN + i], il * il);
    }
}

// Tail half 2: adj_hp scatter + diagonal.
__global__ void k_fin_hp(const int* __restrict__ edges, const float* __restrict__ wlp_out,
                         float* __restrict__ adj_hp) {
    int t = blockIdx.x * blockDim.x + threadIdx.x;
    if (t < EE) {
        if (!g_isw[t]) return;
        int u = edges[t], v = edges[EE + t];
        float wlp = wlp_out[t];
        float ih = g_ihp[u] * g_ihp[v];
        __stcs(&adj_hp[(size_t)u * NN + v],
               (u == v) ? 1.0f - (2.0f - wlp) * ih : -(1.0f - wlp) * ih);
    } else if (t < EE + NN) {
        int i = t - EE;
        if (g_self[i]) return;
        __stcs(&adj_hp[(size_t)i * NN + i], 1.0f);
    }
}

extern "C" void kernel_launch(void* const* d_in, const int* in_sizes, int n_in,
                              void* d_out, int out_size) {
    const float* feat  = (const float*)d_in[0];
    const int*   edges = (const int*)  d_in[1];
    const float* wemb  = (const float*)d_in[2];
    const float* bemb  = (const float*)d_in[3];
    const float* wmlp  = (const float*)d_in[4];
    const float* bmlp  = (const float*)d_in[5];
    const float* gn    = (const float*)d_in[6];

    float* out     = (float*)d_out;
    float* adj_lp  = out;
    float* adj_hp  = out + (size_t)NN * NN;
    float* wlp     = out + 2ull * NN * NN;
    float* whp     = wlp + EE;
    float* unnorm  = whp + EE;

    static cudaStream_t s_sm = nullptr, s_p = nullptr;
    static cudaEvent_t ev_fork = nullptr, ev_fu = nullptr, ev_fa = nullptr,
                       ev_p = nullptr, ev_un = nullptr, ev_chain = nullptr,
                       ev_hp = nullptr;
    if (!s_sm) {
        cudaStreamCreateWithFlags(&s_sm, cudaStreamNonBlocking);
        cudaStreamCreateWithFlags(&s_p,  cudaStreamNonBlocking);
        cudaEventCreateWithFlags(&ev_fork,  cudaEventDisableTiming);
        cudaEventCreateWithFlags(&ev_fu,    cudaEventDisableTiming);
        cudaEventCreateWithFlags(&ev_fa,    cudaEventDisableTiming);
        cudaEventCreateWithFlags(&ev_p,     cudaEventDisableTiming);
        cudaEventCreateWithFlags(&ev_un,    cudaEventDisableTiming);
        cudaEventCreateWithFlags(&ev_chain, cudaEventDisableTiming);
        cudaEventCreateWithFlags(&ev_hp,    cudaEventDisableTiming);
    }

    const int TB = 256;
    const size_t MAT = (size_t)NN * NN;   // elements per matrix
    const int FG = 148 * 16;

    // Fork.
    cudaEventRecord(ev_fork, 0);
    cudaStreamWaitEvent(s_sm, ev_fork, 0);
    cudaStreamWaitEvent(s_p,  ev_fork, 0);

    // Fill stream: unnorm first, then the two adjacency matrices (288 MB).
    k_fill<<<FG, 512, 0, s_sm>>>((float4*)unnorm, MAT / 4);
    cudaEventRecord(ev_fu, s_sm);
    k_fill<<<FG, 512, 0, s_sm>>>((float4*)adj_lp, (2ull * MAT) / 4);
    cudaEventRecord(ev_fa, s_sm);

    // p stream: node scalar projection, then unnorm scatter once its fill lands.
    k_p<<<NN / NPB, HH, 0, s_p>>>(feat, wemb, bemb, wmlp);
    cudaEventRecord(ev_p, s_p);
    cudaStreamWaitEvent(s_p, ev_fu, 0);
    k_fin_unnorm<<<(EE + TB - 1) / TB, TB, 0, s_p>>>(edges, unnorm);
    cudaEventRecord(ev_un, s_p);

    // Main chain: hash clear, dedup, gating, norms (all overlap the fills;
    // all dedup traffic is L2-resident — no dense winner matrix).
    k_clear<<<(EE + TB - 1) / TB, TB>>>();
    k_max  <<<(EE + TB - 1) / TB, TB>>>(edges);
    cudaStreamWaitEvent(0, ev_p, 0);
    k_edge <<<(EE + TB - 1) / TB, TB>>>(edges, gn, bmlp, wlp, whp);
    k_inv  <<<(NN + TB - 1) / TB, TB>>>();
    cudaEventRecord(ev_chain, 0);

    // Split tail AFTER the full fill drain: lp on default stream, hp on s_p —
    // two concurrent latency-bound scatters instead of one serialized kernel.
    const int SG = (EE + NN + TB - 1) / TB;
    cudaStreamWaitEvent(0, ev_fa, 0);
    k_fin_lp<<<SG, TB>>>(edges, wlp, adj_lp);
    cudaStreamWaitEvent(s_p, ev_fa, 0);
    cudaStreamWaitEvent(s_p, ev_chain, 0);
    k_fin_hp<<<SG, TB, 0, s_p>>>(edges, wlp, adj_hp);
    cudaEventRecord(ev_hp, s_p);

    // Join both branches so the graph has a single terminal.
    cudaStreamWaitEvent(0, ev_hp, 0);
    cudaStreamWaitEvent(0, ev_un, 0);
}